// round 6
// baseline (speedup 1.0000x reference)
#include <cuda_runtime.h>

#define L      4096
#define RPB    8                 // rows per block
#define NBLK   (L / RPB)         // 512 blocks
#define NTHR   256
#define GG     (L / 4 / NTHR)    // 4 column-groups of float4 per thread per row

__device__ double g_clash = 0.0;
__device__ double g_p2    = 0.0;   // sum_pmask cv*d2
__device__ double g_pd    = 0.0;   // sum_pmask cv*d
__device__ double g_call  = 0.0;   // sum_all  cv   (n_pairs)
__device__ double g_cnear = 0.0;   // sum_{|sep|<3} cv
__device__ unsigned int g_done = 0;

__device__ __forceinline__ float fsqrt_approx(float x) {
    float r;
    asm("sqrt.approx.f32 %0, %1;" : "=f"(r) : "f"(x));
    return r;
}

__device__ __forceinline__ float nrm3(float x, float y, float z) {
    return fmaf(x, x, fmaf(y, y, z * z));
}

// Exact diff-based clash term. Used by BOTH the voted slow path and the
// near-diagonal correction -> identical inputs + identical ops -> exact cancel.
__device__ __forceinline__ float clash_term(float xi, float yi, float zi,
                                            float xj, float yj, float zj) {
    float dx = xj - xi, dy = yj - yi, dz = zj - zi;
    float d2 = fmaf(dz, dz, fmaf(dy, dy, dx * dx));
    float d  = fsqrt_approx(d2) + 1e-8f;
    float t  = fmaxf(3.4f - d, 0.0f);
    return t * t;
}

__device__ __forceinline__ float warp_sum(float v) {
    v += __shfl_down_sync(0xffffffffu, v, 16);
    v += __shfl_down_sync(0xffffffffu, v, 8);
    v += __shfl_down_sync(0xffffffffu, v, 4);
    v += __shfl_down_sync(0xffffffffu, v, 2);
    v += __shfl_down_sync(0xffffffffu, v, 1);
    return v;
}

__global__ void __launch_bounds__(NTHR, 3)
energy_kernel(const float* __restrict__ coords,
              const float* __restrict__ cmap,
              float* __restrict__ out)
{
    __shared__ float4 rowAB[RPB];   // {-2x, -2y, -2z, |p|^2} per row
    __shared__ float4 rowXYZ[RPB];  // {x, y, z, 0} per row (for exact paths)
    __shared__ float  red[64];

    const int tid = threadIdx.x;
    const int i0  = blockIdx.x * RPB;

    if (tid < RPB) {
        float x = __ldg(coords + 3 * (i0 + tid) + 0);
        float y = __ldg(coords + 3 * (i0 + tid) + 1);
        float z = __ldg(coords + 3 * (i0 + tid) + 2);
        rowXYZ[tid] = make_float4(x, y, z, 0.0f);
        rowAB[tid]  = make_float4(-2.0f * x, -2.0f * y, -2.0f * z, nrm3(x, y, z));
    }
    __syncthreads();

    // split accumulator chains (a/b interleave by e parity)
    float p2a = 0.0f, p2b = 0.0f;   // sum cv*d2
    float pda = 0.0f, pdb = 0.0f;   // sum cv*d
    float call = 0.0f;              // sum cv (all)
    float aclash = 0.0f;            // symmetric clash sum (slow path only)
    float cnear = 0.0f;             // near-band contact count (correction)

    const float4* cp = (const float4*)coords;

#pragma unroll
    for (int gg = 0; gg < GG; ++gg) {
        const int g = tid + gg * NTHR;          // float4 column group: cols 4g..4g+3

        // stage 8 cmap rows first: 8 independent DRAM LDG.128, one base addr
        const float4* cbase = ((const float4*)(cmap + (size_t)i0 * L)) + g;
        float4 c[RPB];
#pragma unroll
        for (int r = 0; r < RPB; ++r) c[r] = __ldg(cbase + r * (L / 4));

        // 4 consecutive j coordinates: 12 contiguous floats = 3x LDG.128 (L2-hot)
        float4 q0 = __ldg(cp + 3 * g + 0);      // x0 y0 z0 x1
        float4 q1 = __ldg(cp + 3 * g + 1);      // y1 z1 x2 y2
        float4 q2 = __ldg(cp + 3 * g + 2);      // z2 x3 y3 z3
        float xj[4] = {q0.x, q0.w, q1.z, q2.y};
        float yj[4] = {q0.y, q1.x, q1.w, q2.z};
        float zj[4] = {q0.z, q1.y, q2.x, q2.w};
        float nj[4];
#pragma unroll
        for (int e = 0; e < 4; ++e) nj[e] = nrm3(xj[e], yj[e], zj[e]);

        float m[4] = {1e30f, 1e30f, 1e30f, 1e30f};

#pragma unroll
        for (int r = 0; r < RPB; ++r) {
            const float4 rd = rowAB[r];         // broadcast LDS.128
            const float4 cc = c[r];
            const float cv[4] = {cc.x, cc.y, cc.z, cc.w};
#pragma unroll
            for (int e = 0; e < 4; ++e) {
                float b  = rd.w + nj[e];
                float t  = fmaf(rd.z, zj[e], b);
                t        = fmaf(rd.y, yj[e], t);
                float d2 = fmaf(rd.x, xj[e], t);      // ni+nj-2 pi.pj
                float d2c = fmaxf(d2, 0.0f);          // diag can go slightly <0
                m[e] = fminf(m[e], d2c);
                float dd = fsqrt_approx(d2c);
                if (e & 1) { p2b = fmaf(cv[e], d2c, p2b); pdb = fmaf(cv[e], dd, pdb); }
                else       { p2a = fmaf(cv[e], d2c, p2a); pda = fmaf(cv[e], dd, pda); }
            }
            call += (cc.x + cc.y) + (cc.z + cc.w);
        }

        // clash only possible where d2 < 11.56 (+margin). Rare -> warp vote.
        float mm = fminf(fminf(m[0], m[1]), fminf(m[2], m[3]));
        if (__any_sync(0xffffffffu, mm < 12.0f)) {
#pragma unroll
            for (int r = 0; r < RPB; ++r) {
                const float4 rx = rowXYZ[r];
#pragma unroll
                for (int e = 0; e < 4; ++e)
                    aclash += clash_term(rx.x, rx.y, rx.z, xj[e], yj[e], zj[e]);
            }
        }
    }

    // Near-diagonal correction for this block's rows: remove |j-i| <= 2 terms.
    // Same helpers + same source values as the main/slow paths -> clean cancel.
    if (tid < RPB * 5) {
        const int r = tid / 5;
        const int o = tid % 5 - 2;
        const int i = i0 + r;
        const int j = i + o;
        if (j >= 0 && j < L) {
            float xj = __ldg(coords + 3 * j + 0);
            float yj = __ldg(coords + 3 * j + 1);
            float zj = __ldg(coords + 3 * j + 2);
            const float4 rx = rowXYZ[r];
            aclash -= clash_term(rx.x, rx.y, rx.z, xj, yj, zj);

            float cv = __ldg(cmap + (size_t)i * L + j);
            const float4 rd = rowAB[r];
            float njj = nrm3(xj, yj, zj);
            float b  = rd.w + njj;
            float t  = fmaf(rd.z, zj, b);
            t        = fmaf(rd.y, yj, t);
            float d2 = fmaf(rd.x, xj, t);
            float d2c = fmaxf(d2, 0.0f);
            float dd  = fsqrt_approx(d2c);
            p2a  -= cv * d2c;
            pda  -= cv * dd;
            cnear += cv;
        }
    }

    // Block reduction: p2, pd, call, cnear, clash
    float rp2 = (p2a + p2b);
    float rpd = (pda + pdb);
    rp2    = warp_sum(rp2);
    rpd    = warp_sum(rpd);
    call   = warp_sum(call);
    cnear  = warp_sum(cnear);
    aclash = warp_sum(aclash);
    const int wid  = tid >> 5;
    const int lane = tid & 31;
    if (lane == 0) {
        red[wid]      = rp2;
        red[8 + wid]  = rpd;
        red[16 + wid] = call;
        red[24 + wid] = cnear;
        red[32 + wid] = aclash;
    }
    __syncthreads();
    if (tid == 0) {
        float s0 = 0.f, s1 = 0.f, s2 = 0.f, s3 = 0.f, s4 = 0.f;
        for (int w = 0; w < 8; ++w) {
            s0 += red[w]; s1 += red[8 + w]; s2 += red[16 + w];
            s3 += red[24 + w]; s4 += red[32 + w];
        }
        atomicAdd(&g_p2,    (double)s0);
        atomicAdd(&g_pd,    (double)s1);
        atomicAdd(&g_call,  (double)s2);
        atomicAdd(&g_cnear, (double)s3);
        atomicAdd(&g_clash, (double)s4);
        __threadfence();
        unsigned prev = atomicAdd(&g_done, 1u);
        red[40] = (prev == (unsigned)(NBLK - 1)) ? 1.0f : 0.0f;
    }
    __syncthreads();

    // Last block: bond term + finalize + reset accumulators for next replay
    if (red[40] != 0.0f) {
        float bsum = 0.0f;
        for (int k = tid; k < L - 1; k += NTHR) {
            float dx = __ldg(coords + 3 * k + 3) - __ldg(coords + 3 * k + 0);
            float dy = __ldg(coords + 3 * k + 4) - __ldg(coords + 3 * k + 1);
            float dz = __ldg(coords + 3 * k + 5) - __ldg(coords + 3 * k + 2);
            float d  = fsqrt_approx(fmaf(dz, dz, fmaf(dy, dy, dx * dx)));
            float t  = d - 6.0f;               // IDEAL_C1_C1
            bsum = fmaf(t, t, bsum);
        }
        bsum = warp_sum(bsum);
        if (lane == 0) red[48 + wid] = bsum;
        __syncthreads();
        if (tid == 0) {
            float bs = 0.0f;
            for (int w = 0; w < 8; ++w) bs += red[48 + w];
            double e_bond  = (double)bs / (double)(L - 1);
            double e_clash = (g_clash * 0.5) / (double)L;     // sym sum -> upper triangle
            double npairs  = g_call < 1.0 ? 1.0 : g_call;
            // (d-9)^2 = d2 - 18 d + 81, over pmask pairs
            double num     = g_p2 - 18.0 * g_pd + 81.0 * (g_call - g_cnear);
            double e_pair  = num / npairs;
            out[0] = (float)(e_bond + 2.0 * e_clash + 0.5 * e_pair);
            // reset for next graph replay
            g_p2 = 0.0; g_pd = 0.0; g_call = 0.0; g_cnear = 0.0; g_clash = 0.0;
            g_done = 0u;
        }
    }
}

extern "C" void kernel_launch(void* const* d_in, const int* in_sizes, int n_in,
                              void* d_out, int out_size) {
    const float* a0 = (const float*)d_in[0];
    const float* a1 = (const float*)d_in[1];
    // coords is the small input (L*3), contact_map the big one (L*L)
    const float* coords = (in_sizes[0] < in_sizes[1]) ? a0 : a1;
    const float* cmap   = (in_sizes[0] < in_sizes[1]) ? a1 : a0;
    energy_kernel<<<NBLK, NTHR>>>(coords, cmap, (float*)d_out);
}

// round 7
// speedup vs baseline: 2.1586x; 2.1586x over previous
#include <cuda_runtime.h>

#define L      4096
#define RPB    8                    // rows per block
#define HALF   2048                 // columns per block (half the row)
#define NTHR   256
#define GG     (HALF / 4 / NTHR)    // 2 float4 column-groups per thread
#define NBLK   ((L / RPB) * 2)      // 1024 blocks (row-block x column-half)

__device__ double g_clash = 0.0;
__device__ double g_pair  = 0.0;
__device__ double g_cnt   = 0.0;
__device__ unsigned int g_done = 0;

__device__ __forceinline__ float fsqrt_approx(float x) {
    float r;
    asm("sqrt.approx.f32 %0, %1;" : "=f"(r) : "f"(x));
    return r;
}

__device__ __forceinline__ float warp_sum(float v) {
    v += __shfl_down_sync(0xffffffffu, v, 16);
    v += __shfl_down_sync(0xffffffffu, v, 8);
    v += __shfl_down_sync(0xffffffffu, v, 4);
    v += __shfl_down_sync(0xffffffffu, v, 2);
    v += __shfl_down_sync(0xffffffffu, v, 1);
    return v;
}

__global__ void __launch_bounds__(NTHR, 4)
energy_kernel(const float* __restrict__ coords,
              const float* __restrict__ cmap,
              float* __restrict__ out)
{
    __shared__ float red[64];
    const int tid  = threadIdx.x;
    const int rb   = blockIdx.x >> 1;        // row block
    const int half = blockIdx.x & 1;         // column half
    const int i0   = rb * RPB;

    // Row coordinates for this block's 8 rows (broadcast loads, L1-hot)
    float xi[RPB], yi[RPB], zi[RPB];
#pragma unroll
    for (int r = 0; r < RPB; ++r) {
        xi[r] = __ldg(coords + 3 * (i0 + r) + 0);
        yi[r] = __ldg(coords + 3 * (i0 + r) + 1);
        zi[r] = __ldg(coords + 3 * (i0 + r) + 2);
    }

    float a_clash = 0.0f;   // includes |sep|<3 terms (corrected below)
    float a_pair  = 0.0f;
    float a_cnt   = 0.0f;   // sum of contact values (exact 0/1)

    const float4* cp = (const float4*)coords;

#pragma unroll
    for (int gg = 0; gg < GG; ++gg) {
        const int g = half * (HALF / 4) + gg * NTHR + tid;  // float4 column group

        // stage 8 cmap rows first: 8 independent DRAM LDG.128, one base addr
        const float4* cbase = ((const float4*)(cmap + (size_t)i0 * L)) + g;
        float4 c[RPB];
#pragma unroll
        for (int r = 0; r < RPB; ++r) c[r] = __ldg(cbase + r * (L / 4));

        // 4 consecutive j coordinates: 12 contiguous floats = 3x LDG.128 (L2-hot)
        float4 q0 = __ldg(cp + 3 * g + 0);      // x0 y0 z0 x1
        float4 q1 = __ldg(cp + 3 * g + 1);      // y1 z1 x2 y2
        float4 q2 = __ldg(cp + 3 * g + 2);      // z2 x3 y3 z3
        float xj[4] = {q0.x, q0.w, q1.z, q2.y};
        float yj[4] = {q0.y, q1.x, q1.w, q2.z};
        float zj[4] = {q0.z, q1.y, q2.x, q2.w};

#pragma unroll
        for (int r = 0; r < RPB; ++r) {
            const float4 cc = c[r];
            a_cnt += (cc.x + cc.y) + (cc.z + cc.w);
            float cv[4] = {cc.x, cc.y, cc.z, cc.w};
#pragma unroll
            for (int e = 0; e < 4; ++e) {
                float dx = xj[e] - xi[r];
                float dy = yj[e] - yi[r];
                float dz = zj[e] - zi[r];
                float d2 = fmaf(dz, dz, fmaf(dy, dy, dx * dx));
                float d  = fsqrt_approx(d2) + 1e-8f;
                float t  = fmaxf(3.4f - d, 0.0f);
                a_clash  = fmaf(t, t, a_clash);
                float u  = d - 9.0f;             // target_dist = 6.0 * 1.5
                float w  = u * cv[e];            // contact mask via multiply (cv in {0,1})
                a_pair   = fmaf(w, u, a_pair);
            }
        }
    }

    // Near-diagonal correction: remove |j-i| <= 2 terms. Only the column half
    // that owns column j performs it. Same fp expressions as the main loop.
    if (tid < RPB * 5) {
        const int r = tid / 5;
        const int o = tid % 5 - 2;
        const int i = i0 + r;
        const int j = i + o;
        if (j >= 0 && j < L && ((j >> 11) == half)) {
            float xJ = __ldg(coords + 3 * j + 0);
            float yJ = __ldg(coords + 3 * j + 1);
            float zJ = __ldg(coords + 3 * j + 2);
            float dx = xJ - xi[r], dy = yJ - yi[r], dz = zJ - zi[r];
            float d2 = fmaf(dz, dz, fmaf(dy, dy, dx * dx));
            float d  = fsqrt_approx(d2) + 1e-8f;
            float t  = fmaxf(3.4f - d, 0.0f);
            a_clash -= t * t;
            float cv = __ldg(cmap + (size_t)i * L + j);
            float u  = d - 9.0f;
            float w  = u * cv;
            a_pair   = fmaf(-w, u, a_pair);
        }
    }

    // Block reduction
    a_clash = warp_sum(a_clash);
    a_pair  = warp_sum(a_pair);
    a_cnt   = warp_sum(a_cnt);
    const int wid  = tid >> 5;
    const int lane = tid & 31;
    if (lane == 0) {
        red[wid]      = a_clash;
        red[8 + wid]  = a_pair;
        red[16 + wid] = a_cnt;
    }
    __syncthreads();
    if (tid == 0) {
        float cs = 0.0f, ps = 0.0f, ns = 0.0f;
        for (int w = 0; w < 8; ++w) { cs += red[w]; ps += red[8 + w]; ns += red[16 + w]; }
        atomicAdd(&g_clash, (double)cs);
        atomicAdd(&g_pair,  (double)ps);
        atomicAdd(&g_cnt,   (double)ns);
        __threadfence();
        unsigned prev = atomicAdd(&g_done, 1u);
        red[24] = (prev == (unsigned)(NBLK - 1)) ? 1.0f : 0.0f;
    }
    __syncthreads();

    // Last block: bond term + finalize + reset accumulators for next replay
    if (red[24] != 0.0f) {
        float b = 0.0f;
        for (int k = tid; k < L - 1; k += NTHR) {
            float dx = __ldg(coords + 3 * k + 3) - __ldg(coords + 3 * k + 0);
            float dy = __ldg(coords + 3 * k + 4) - __ldg(coords + 3 * k + 1);
            float dz = __ldg(coords + 3 * k + 5) - __ldg(coords + 3 * k + 2);
            float d  = fsqrt_approx(fmaf(dz, dz, fmaf(dy, dy, dx * dx)));
            float t  = d - 6.0f;               // IDEAL_C1_C1
            b = fmaf(t, t, b);
        }
        b = warp_sum(b);
        if (lane == 0) red[32 + wid] = b;
        __syncthreads();
        if (tid == 0) {
            float bs = 0.0f;
            for (int w = 0; w < 8; ++w) bs += red[32 + w];
            double e_bond  = (double)bs / (double)(L - 1);
            double e_clash = (g_clash * 0.5) / (double)L;     // sym sum -> upper triangle
            double cnt     = g_cnt < 1.0 ? 1.0 : g_cnt;
            double e_pair  = g_pair / cnt;
            out[0] = (float)(e_bond + 2.0 * e_clash + 0.5 * e_pair);
            // reset for next graph replay
            g_clash = 0.0;
            g_pair  = 0.0;
            g_cnt   = 0.0;
            g_done  = 0u;
        }
    }
}

extern "C" void kernel_launch(void* const* d_in, const int* in_sizes, int n_in,
                              void* d_out, int out_size) {
    const float* a0 = (const float*)d_in[0];
    const float* a1 = (const float*)d_in[1];
    // coords is the small input (L*3), contact_map the big one (L*L)
    const float* coords = (in_sizes[0] < in_sizes[1]) ? a0 : a1;
    const float* cmap   = (in_sizes[0] < in_sizes[1]) ? a1 : a0;
    energy_kernel<<<NBLK, NTHR>>>(coords, cmap, (float*)d_out);
}